// round 9
// baseline (speedup 1.0000x reference)
#include <cuda_runtime.h>
#include <math.h>

#define B_     16
#define CH_    22
#define T_     1001
#define F_     36
#define KT_    65
#define T1_    937            // T - KT + 1
#define T1P_   944            // padded stride
#define GC_    (F_*CH_)       // 792
#define KC_    15
#define U_     885            // E length
#define UP_    888            // padded stride
#define SLEN_  935            // S length
#define SP_    944            // S padded stride
#define Q_     43
#define NCROPS_ 501
#define OUT_   4
#define FLAT_  (F_*Q_)        // 1548
#define EPSF   1e-5f

#define KSPLIT2_ 8
#define KCHUNK2_ (GC_/KSPLIT2_)   // 99
#define KPAD2_   104              // padded rows (prefetch over-run, zero weights)
#define GSPLIT3_ 6
#define GCHUNK3_ (F_/GSPLIT3_)    // 6

typedef unsigned long long ull;

// ---------------- scratch (device globals; no allocation) ----------------
__device__ float d_h1[(size_t)B_*GC_*T1P_ + 16384]; // temporal act [b][f*CH+ch][t] (+OOB pad for prefetch)
__device__ float d_p2[(size_t)KSPLIT2_*B_*F_*T1P_]; // k2 partials [s][b][f][t]
__device__ float d_S [(size_t)B_*F_*SP_];           // 3-mean of elu(bn(spatial)) [b][f][t]
__device__ float d_p3[(size_t)GSPLIT3_*B_*F_*UP_];  // k3 partials [gs][b][f][u]
__device__ float d_G [(size_t)B_*FLAT_];            // summed pool2 [b][f*43+q]

// ---------------- f32x2 helpers ----------------
__device__ __forceinline__ ull pack2(float a, float b) {
    ull r;
    asm("mov.b64 %0, {%1, %2};" : "=l"(r) : "f"(a), "f"(b));
    return r;
}
__device__ __forceinline__ void fma2(ull& d, ull a, ull b) {
    asm("fma.rn.f32x2 %0, %1, %2, %0;" : "+l"(d) : "l"(a), "l"(b));
}
__device__ __forceinline__ float2 unpack2(ull v) {
    float2 r;
    asm("mov.b64 {%0, %1}, %2;" : "=f"(r.x), "=f"(r.y) : "l"(v));
    return r;
}
__device__ __forceinline__ float eluf(float x) {
    return x > 0.0f ? x : (__expf(x) - 1.0f);
}
__device__ __forceinline__ void bn_fold(const float* bi, const float* g, const float* bb,
                                        const float* m, const float* v, int f,
                                        float& sc, float& sh) {
    float inv = g[f] / sqrtf(v[f] + EPSF);
    sc = inv;
    sh = (bi[f] - m[f]) * inv + bb[f];
}

// ---------------- K1: temporal conv + BN + ELU ----------------
// grid (2*3, CH, B), block 128. Thread: 4 t-slots (tid+128m) x 12 f (6 f32x2 pairs).
__global__ void __launch_bounds__(128) k1_temporal(
    const float* __restrict__ x, const float* __restrict__ w_t,
    const float* __restrict__ b_t, const float* __restrict__ g_t,
    const float* __restrict__ bb_t, const float* __restrict__ m_t,
    const float* __restrict__ v_t)
{
    __shared__ ull sx2[576];               // duplicated (v,v) pairs
    __shared__ ull sw[KT_][6];             // f-pairs (w_f, w_f+1)
    const int b   = blockIdx.z;
    const int ch  = blockIdx.y;
    const int tb  = blockIdx.x / 3;
    const int fg  = blockIdx.x % 3;
    const int f0  = fg * 12;
    const int t0  = tb * 512;
    const int tid = threadIdx.x;

    for (int i = tid; i < KT_ * 6; i += 128) {
        int k = i / 6, p = i % 6;
        sw[k][p] = pack2(w_t[(f0 + 2*p) * KT_ + k],
                         w_t[(f0 + 2*p + 1) * KT_ + k]);
    }
    const float* xp = x + ((size_t)b * CH_ + ch) * T_;
    for (int i = tid; i < 576; i += 128) {
        int tg = t0 + i;
        float v = (tg < T_) ? xp[tg] : 0.0f;
        sx2[i] = pack2(v, v);
    }
    __syncthreads();

    ull acc[4][6];
#pragma unroll
    for (int m = 0; m < 4; m++)
#pragma unroll
        for (int p = 0; p < 6; p++) acc[m][p] = 0ULL;

#pragma unroll 5
    for (int k = 0; k < KT_; k++) {
        ull x0 = sx2[tid + k];
        ull x1 = sx2[tid + 128 + k];
        ull x2 = sx2[tid + 256 + k];
        ull x3 = sx2[tid + 384 + k];
        ulonglong2 w01 = *(const ulonglong2*)&sw[k][0];
        ulonglong2 w23 = *(const ulonglong2*)&sw[k][2];
        ulonglong2 w45 = *(const ulonglong2*)&sw[k][4];
        ull wv[6] = {w01.x, w01.y, w23.x, w23.y, w45.x, w45.y};
#pragma unroll
        for (int p = 0; p < 6; p++) {
            fma2(acc[0][p], x0, wv[p]);
            fma2(acc[1][p], x1, wv[p]);
            fma2(acc[2][p], x2, wv[p]);
            fma2(acc[3][p], x3, wv[p]);
        }
    }

    float sc[12], sh[12];
#pragma unroll
    for (int fl = 0; fl < 12; fl++)
        bn_fold(b_t, g_t, bb_t, m_t, v_t, f0 + fl, sc[fl], sh[fl]);

#pragma unroll
    for (int m = 0; m < 4; m++) {
        int t = t0 + 128 * m + tid;
        if (t < T1_) {
#pragma unroll
            for (int p = 0; p < 6; p++) {
                float2 a = unpack2(acc[m][p]);
                int fA = f0 + 2*p, fB = fA + 1;
                d_h1[((size_t)b * GC_ + (size_t)fA * CH_ + ch) * T1P_ + t]
                    = eluf(fmaf(a.x, sc[2*p], sh[2*p]));
                d_h1[((size_t)b * GC_ + (size_t)fB * CH_ + ch) * T1P_ + t]
                    = eluf(fmaf(a.y, sc[2*p + 1], sh[2*p + 1]));
            }
        }
    }
}

// ---------------- K2: spatial conv, split-K partials ----------------
// grid (4 t-tiles x 236, 3 f-groups, B*8 splits), block 64.
// Thread: 4 consecutive t (2 packed t-pairs) x 12 f. h1 via LDG.128 with depth-4 prefetch ring.
__global__ void __launch_bounds__(64) k2_spatial(const float* __restrict__ w_s)
{
    __shared__ ull sw2[KPAD2_][12];        // duplicated (w,w) per f; rows >= 99 zero pad
    const int b   = blockIdx.z >> 3;
    const int s   = blockIdx.z & 7;
    const int f0  = blockIdx.y * 12;
    const int t0  = blockIdx.x * 236;
    const int tid = threadIdx.x;
    const int ks0 = s * KCHUNK2_;

    for (int i = tid; i < KPAD2_ * 12; i += 64) {
        int k = i / 12, f = i % 12;
        float w = (k < KCHUNK2_) ? w_s[(size_t)(f0 + f) * GC_ + ks0 + k] : 0.0f;
        sw2[k][f] = pack2(w, w);
    }
    __syncthreads();

    const int t = t0 + tid * 4;
    const float* base = d_h1 + ((size_t)(b * GC_ + ks0)) * T1P_ + t;

    ull acc[12][2];
#pragma unroll
    for (int f = 0; f < 12; f++) { acc[f][0] = 0ULL; acc[f][1] = 0ULL; }

    ulonglong2 hbuf[4];
#pragma unroll
    for (int j = 0; j < 4; j++)
        hbuf[j] = *(const ulonglong2*)(base + (size_t)j * T1P_);

#pragma unroll 1
    for (int k0 = 0; k0 < 100; k0 += 4) {
#pragma unroll
        for (int j = 0; j < 4; j++) {
            const int k = k0 + j;
            ulonglong2 h = hbuf[j];
            hbuf[j] = *(const ulonglong2*)(base + (size_t)(k + 4) * T1P_);
#pragma unroll
            for (int pf = 0; pf < 6; pf++) {
                ulonglong2 w = *(const ulonglong2*)&sw2[k][2 * pf];
                fma2(acc[2*pf][0],     h.x, w.x);
                fma2(acc[2*pf][1],     h.y, w.x);
                fma2(acc[2*pf + 1][0], h.x, w.y);
                fma2(acc[2*pf + 1][1], h.y, w.y);
            }
        }
    }

    if (t < T1_) {
        float* pb = d_p2 + ((size_t)s * B_ * F_ + (size_t)b * F_) * T1P_;
        const bool full = (t + 3 < T1_);
#pragma unroll
        for (int f = 0; f < 12; f++) {
            float* row = pb + (size_t)(f0 + f) * T1P_;
            if (full) {
                ulonglong2 v; v.x = acc[f][0]; v.y = acc[f][1];
                *(ulonglong2*)&row[t] = v;
            } else {
                float2 a0 = unpack2(acc[f][0]);
                float2 a1 = unpack2(acc[f][1]);
                float vals[4] = {a0.x, a0.y, a1.x, a1.y};
                for (int j = 0; j < 4; j++)
                    if (t + j < T1_) row[t + j] = vals[j];
            }
        }
    }
}

// ---------------- K2e: reduce 8 partials + BN + ELU + 3-mean -> S ----------------
// grid (F, B), block 128. Vectorized float4.
__global__ void __launch_bounds__(128) k2e_reduce(
    const float* __restrict__ b_s, const float* __restrict__ g_s,
    const float* __restrict__ bb_s, const float* __restrict__ m_s,
    const float* __restrict__ v_s)
{
    __shared__ float e[T1P_];
    const int b = blockIdx.y, f = blockIdx.x;
    const int tid = threadIdx.x;
    const size_t row = ((size_t)b * F_ + f) * T1P_;
    const size_t ps = (size_t)B_ * F_ * T1P_;
    float sc, sh;
    bn_fold(b_s, g_s, bb_s, m_s, v_s, f, sc, sh);

    for (int i = tid; i < T1P_ / 4; i += 128) {
        float4 a = *(const float4*)&d_p2[row + 4 * i];
        float4 sum = a;
#pragma unroll
        for (int p = 1; p < KSPLIT2_; p++) {
            float4 v = *(const float4*)&d_p2[(size_t)p * ps + row + 4 * i];
            sum.x += v.x; sum.y += v.y; sum.z += v.z; sum.w += v.w;
        }
        float4 r;
        r.x = eluf(fmaf(sum.x, sc, sh));
        r.y = eluf(fmaf(sum.y, sc, sh));
        r.z = eluf(fmaf(sum.z, sc, sh));
        r.w = eluf(fmaf(sum.w, sc, sh));
        *(float4*)&e[4 * i] = r;
    }
    __syncthreads();

    float* Sp = d_S + ((size_t)b * F_ + f) * SP_;
    for (int tt = tid; tt < SLEN_; tt += 128)
        Sp[tt] = (e[tt] + e[tt + 1] + e[tt + 2]) * (1.0f / 3.0f);
}

// ---------------- K3: dilation-3 conv, split-g partials ----------------
// grid (4 u-tiles x 256, 3 f-groups, B*6 g-splits), block 128.
// Thread: 2 u-slots (tid, tid+128) x 12 f (6 pairs). S duplicated in smem.
__global__ void __launch_bounds__(128) k3_dconv(const float* __restrict__ w_c)
{
    __shared__ ull sS2[GCHUNK3_][304];              // dup (s,s); window 299 used
    __shared__ ull sw[GCHUNK3_ * KC_][6];           // f-pairs
    const int b   = blockIdx.z / GSPLIT3_;
    const int gs  = blockIdx.z % GSPLIT3_;
    const int f0  = blockIdx.y * 12;
    const int g0  = gs * GCHUNK3_;
    const int u0  = blockIdx.x * 256;
    const int tid = threadIdx.x;

    for (int i = tid; i < GCHUNK3_ * 299; i += 128) {
        int g = i / 299, kk = i % 299;
        int tt = u0 + kk;
        float v = (tt < SLEN_) ? d_S[((size_t)b * F_ + g0 + g) * SP_ + tt] : 0.0f;
        sS2[g][kk] = pack2(v, v);
    }
    for (int i = tid; i < GCHUNK3_ * KC_ * 6; i += 128) {
        int idx = i / 6, p = i % 6;
        int g = idx / KC_, j = idx % KC_;
        sw[idx][p] = pack2(w_c[((size_t)(f0 + 2*p) * F_ + g0 + g) * KC_ + j],
                           w_c[((size_t)(f0 + 2*p + 1) * F_ + g0 + g) * KC_ + j]);
    }
    __syncthreads();

    ull acc0[6], acc1[6];
#pragma unroll
    for (int p = 0; p < 6; p++) { acc0[p] = 0ULL; acc1[p] = 0ULL; }

#pragma unroll 1
    for (int g = 0; g < GCHUNK3_; g++) {
#pragma unroll
        for (int j = 0; j < KC_; j++) {
            ull s0 = sS2[g][tid + 3 * j];
            ull s1 = sS2[g][tid + 128 + 3 * j];
            ulonglong2 w01 = *(const ulonglong2*)&sw[g * KC_ + j][0];
            ulonglong2 w23 = *(const ulonglong2*)&sw[g * KC_ + j][2];
            ulonglong2 w45 = *(const ulonglong2*)&sw[g * KC_ + j][4];
            fma2(acc0[0], s0, w01.x); fma2(acc1[0], s1, w01.x);
            fma2(acc0[1], s0, w01.y); fma2(acc1[1], s1, w01.y);
            fma2(acc0[2], s0, w23.x); fma2(acc1[2], s1, w23.x);
            fma2(acc0[3], s0, w23.y); fma2(acc1[3], s1, w23.y);
            fma2(acc0[4], s0, w45.x); fma2(acc1[4], s1, w45.x);
            fma2(acc0[5], s0, w45.y); fma2(acc1[5], s1, w45.y);
        }
    }

    float* pb = d_p3 + ((size_t)gs * B_ * F_ + (size_t)b * F_) * UP_;
#pragma unroll
    for (int m = 0; m < 2; m++) {
        int u = u0 + 128 * m + tid;
        if (u < U_) {
            const ull* ac = m ? acc1 : acc0;
#pragma unroll
            for (int p = 0; p < 6; p++) {
                float2 a = unpack2(ac[p]);
                pb[(size_t)(f0 + 2*p) * UP_ + u]     = a.x;
                pb[(size_t)(f0 + 2*p + 1) * UP_ + u] = a.y;
            }
        }
    }
}

// ---------------- K4: reduce 6 partials + BN + ELU + prefix scan + windows -> G ----------------
// grid (F, B), block 1024. Warp-shuffle 3-phase scan.
__global__ void __launch_bounds__(1024) k4_windows(
    const float* __restrict__ b_c, const float* __restrict__ g_c,
    const float* __restrict__ bb_c, const float* __restrict__ m_c,
    const float* __restrict__ v_c)
{
    __shared__ float wsum[32];
    __shared__ float ps[1025];
    const int b = blockIdx.y, f = blockIdx.x;
    const int tid = threadIdx.x;
    const int lane = tid & 31, wid = tid >> 5;
    const size_t row = ((size_t)b * F_ + f) * UP_;
    const size_t pstride = (size_t)B_ * F_ * UP_;
    float sc, sh;
    bn_fold(b_c, g_c, bb_c, m_c, v_c, f, sc, sh);

    float e = 0.0f;
    if (tid < U_) {
        float v = d_p3[row + tid];
#pragma unroll
        for (int p = 1; p < GSPLIT3_; p++)
            v += d_p3[(size_t)p * pstride + row + tid];
        e = eluf(fmaf(v, sc, sh));
    }

    float xv = e;
#pragma unroll
    for (int off = 1; off < 32; off <<= 1) {
        float y = __shfl_up_sync(0xffffffffu, xv, off);
        if (lane >= off) xv += y;
    }
    if (lane == 31) wsum[wid] = xv;
    __syncthreads();
    if (wid == 0) {
        float sv = wsum[lane];
#pragma unroll
        for (int off = 1; off < 32; off <<= 1) {
            float y = __shfl_up_sync(0xffffffffu, sv, off);
            if (lane >= off) sv += y;
        }
        wsum[lane] = sv;
    }
    __syncthreads();
    float base = (wid > 0) ? wsum[wid - 1] : 0.0f;
    ps[tid + 1] = xv + base;
    if (tid == 0) ps[0] = 0.0f;
    __syncthreads();

    if (tid < Q_) {
        int q = tid;
        float s = 0.0f;
#pragma unroll
        for (int c = 0; c <= 6; c += 3)
            s += ps[9 * q + c + 501] - ps[9 * q + c];
        d_G[(size_t)b * FLAT_ + f * Q_ + q] = s * (1.0f / 3.0f);
    }
}

// ---------------- K5: FC reduce ----------------
__global__ void __launch_bounds__(128) k5_fc(
    const float* __restrict__ w_fc, const float* __restrict__ b_fc,
    float* __restrict__ out)
{
    __shared__ float red[OUT_][128];
    const int b = blockIdx.x;
    const int tid = threadIdx.x;

    float p[OUT_];
#pragma unroll
    for (int o = 0; o < OUT_; o++) p[o] = 0.0f;

    for (int i = tid; i < FLAT_; i += 128) {
        float g = d_G[(size_t)b * FLAT_ + i];
#pragma unroll
        for (int o = 0; o < OUT_; o++)
            p[o] = fmaf(g, w_fc[(size_t)o * FLAT_ + i], p[o]);
    }
#pragma unroll
    for (int o = 0; o < OUT_; o++) red[o][tid] = p[o];
    __syncthreads();
    for (int s = 64; s > 0; s >>= 1) {
        if (tid < s) {
#pragma unroll
            for (int o = 0; o < OUT_; o++) red[o][tid] += red[o][tid + s];
        }
        __syncthreads();
    }
    if (tid < OUT_)
        out[b * OUT_ + tid] = red[tid][0] * (1.0f / NCROPS_) + b_fc[tid];
}

// ---------------- launch ----------------
extern "C" void kernel_launch(void* const* d_in, const int* in_sizes, int n_in,
                              void* d_out, int out_size)
{
    const float* x      = (const float*)d_in[0];
    const float* w_t    = (const float*)d_in[1];
    const float* b_t    = (const float*)d_in[2];
    const float* bn_t_g = (const float*)d_in[3];
    const float* bn_t_b = (const float*)d_in[4];
    const float* bn_t_m = (const float*)d_in[5];
    const float* bn_t_v = (const float*)d_in[6];
    const float* w_s    = (const float*)d_in[7];
    const float* b_s    = (const float*)d_in[8];
    const float* bn_s_g = (const float*)d_in[9];
    const float* bn_s_b = (const float*)d_in[10];
    const float* bn_s_m = (const float*)d_in[11];
    const float* bn_s_v = (const float*)d_in[12];
    const float* w_c    = (const float*)d_in[13];
    const float* b_c    = (const float*)d_in[14];
    const float* bn_c_g = (const float*)d_in[15];
    const float* bn_c_b = (const float*)d_in[16];
    const float* bn_c_m = (const float*)d_in[17];
    const float* bn_c_v = (const float*)d_in[18];
    const float* w_fc   = (const float*)d_in[19];
    const float* b_fc   = (const float*)d_in[20];
    float* out = (float*)d_out;

    dim3 g1(6, CH_, B_);                      // 2112 blocks
    k1_temporal<<<g1, 128>>>(x, w_t, b_t, bn_t_g, bn_t_b, bn_t_m, bn_t_v);

    dim3 g2(4, 3, B_ * KSPLIT2_);             // 1536 blocks, 64 thr
    k2_spatial<<<g2, 64>>>(w_s);

    dim3 g2e(F_, B_);                         // 576 blocks
    k2e_reduce<<<g2e, 128>>>(b_s, bn_s_g, bn_s_b, bn_s_m, bn_s_v);

    dim3 g3(4, 3, B_ * GSPLIT3_);             // 1152 blocks
    k3_dconv<<<g3, 128>>>(w_c);

    dim3 g4(F_, B_);                          // 576 blocks
    k4_windows<<<g4, 1024>>>(b_c, bn_c_g, bn_c_b, bn_c_m, bn_c_v);

    k5_fc<<<B_, 128>>>(w_fc, b_fc, out);
}

// round 10
// speedup vs baseline: 1.0491x; 1.0491x over previous
#include <cuda_runtime.h>
#include <math.h>

#define B_     16
#define CH_    22
#define T_     1001
#define F_     36
#define KT_    65
#define T1_    937            // T - KT + 1
#define T1P_   944            // padded stride
#define GC_    (F_*CH_)       // 792
#define KC_    15
#define U_     885            // E length
#define SLEN_  935            // S length
#define Q_     43
#define NCROPS_ 501
#define OUT_   4
#define FLAT_  (F_*Q_)        // 1548
#define EPSF   1e-5f

#define KSPLIT2_ 4
#define KCHUNK2_ (GC_/KSPLIT2_)   // 198

// de-interleaved (residue) layout
#define MC_   295             // valid m per residue (u = 3m+c < 885)
#define MS_   312             // S_c row stride (floats); m' 0..311
#define EC_   296             // E_c row stride

typedef unsigned long long ull;

// ---------------- scratch (device globals; no allocation) ----------------
__device__ float d_h1[(size_t)B_*GC_*T1P_ + 8192]; // temporal act [b][f*CH+ch][t] (+OOB pad for prefetch)
__device__ float d_p2[(size_t)KSPLIT2_*B_*F_*T1P_]; // k2 partials [s][b][f][t]
__device__ float d_Sc[(size_t)B_*F_*3*MS_];         // de-interleaved 3-mean [b][f][c][m]
__device__ float d_Ec[(size_t)B_*F_*3*EC_];         // elu(bn(D)) de-interleaved [b][f][c][m]
__device__ float d_G [(size_t)B_*FLAT_];            // summed pool2 [b][f*43+q]
__device__ float d_scale_t[F_], d_shift_t[F_];
__device__ float d_scale_s[F_], d_shift_s[F_];
__device__ float d_scale_c[F_], d_shift_c[F_];

// ---------------- f32x2 helpers ----------------
__device__ __forceinline__ ull pack2(float a, float b) {
    ull r;
    asm("mov.b64 %0, {%1, %2};" : "=l"(r) : "f"(a), "f"(b));
    return r;
}
__device__ __forceinline__ void fma2(ull& d, ull a, ull b) {
    asm("fma.rn.f32x2 %0, %1, %2, %0;" : "+l"(d) : "l"(a), "l"(b));
}
__device__ __forceinline__ float2 unpack2(ull v) {
    float2 r;
    asm("mov.b64 {%0, %1}, %2;" : "=f"(r.x), "=f"(r.y) : "l"(v));
    return r;
}
__device__ __forceinline__ float eluf(float x) {
    return x > 0.0f ? x : (__expf(x) - 1.0f);
}

// ---------------- prep: fold bias + BN ----------------
__global__ void prep_kernel(
    const float* __restrict__ b_t, const float* __restrict__ g_t, const float* __restrict__ bb_t,
    const float* __restrict__ m_t, const float* __restrict__ v_t,
    const float* __restrict__ b_s, const float* __restrict__ g_s, const float* __restrict__ bb_s,
    const float* __restrict__ m_s, const float* __restrict__ v_s,
    const float* __restrict__ b_c, const float* __restrict__ g_c, const float* __restrict__ bb_c,
    const float* __restrict__ m_c, const float* __restrict__ v_c)
{
    int i = threadIdx.x;
    if (i < F_) {
        float inv;
        inv = g_t[i] / sqrtf(v_t[i] + EPSF);
        d_scale_t[i] = inv; d_shift_t[i] = (b_t[i] - m_t[i]) * inv + bb_t[i];
        inv = g_s[i] / sqrtf(v_s[i] + EPSF);
        d_scale_s[i] = inv; d_shift_s[i] = (b_s[i] - m_s[i]) * inv + bb_s[i];
        inv = g_c[i] / sqrtf(v_c[i] + EPSF);
        d_scale_c[i] = inv; d_shift_c[i] = (b_c[i] - m_c[i]) * inv + bb_c[i];
    }
}

// ---------------- K1: temporal conv + BN + ELU (unchanged from 115us best) ----------------
__global__ void __launch_bounds__(128) k1_temporal(
    const float* __restrict__ x, const float* __restrict__ w_t)
{
    __shared__ float sx[512 + 64];         // 576
    __shared__ ull   sw[KT_][6];           // f32x2 weight pairs
    const int b   = blockIdx.z;
    const int ch  = blockIdx.y;
    const int tb  = blockIdx.x / 3;
    const int fg  = blockIdx.x % 3;
    const int f0  = fg * 12;
    const int t0  = tb * 512;
    const int tid = threadIdx.x;

    for (int i = tid; i < KT_ * 6; i += 128) {
        int k = i / 6, p = i % 6;
        sw[k][p] = pack2(w_t[(f0 + 2*p) * KT_ + k],
                         w_t[(f0 + 2*p + 1) * KT_ + k]);
    }
    const float* xp = x + ((size_t)b * CH_ + ch) * T_;
    for (int i = tid; i < 576; i += 128) {
        int tg = t0 + i;
        sx[i] = (tg < T_) ? xp[tg] : 0.0f;
    }
    __syncthreads();

    ull acc[4][6];
#pragma unroll
    for (int m = 0; m < 4; m++)
#pragma unroll
        for (int p = 0; p < 6; p++) acc[m][p] = 0ULL;

    const int tb4 = tid * 4;
#pragma unroll 5
    for (int k = 0; k < KT_; k++) {
        float x0 = sx[tb4 + k];
        float x1 = sx[tb4 + k + 1];
        float x2 = sx[tb4 + k + 2];
        float x3 = sx[tb4 + k + 3];
        ull xp0 = pack2(x0, x0), xp1 = pack2(x1, x1);
        ull xp2 = pack2(x2, x2), xp3 = pack2(x3, x3);
        ulonglong2 w01 = *(const ulonglong2*)&sw[k][0];
        ulonglong2 w23 = *(const ulonglong2*)&sw[k][2];
        ulonglong2 w45 = *(const ulonglong2*)&sw[k][4];
        ull wv[6] = {w01.x, w01.y, w23.x, w23.y, w45.x, w45.y};
#pragma unroll
        for (int p = 0; p < 6; p++) {
            fma2(acc[0][p], xp0, wv[p]);
            fma2(acc[1][p], xp1, wv[p]);
            fma2(acc[2][p], xp2, wv[p]);
            fma2(acc[3][p], xp3, wv[p]);
        }
    }

    const int tbase = t0 + tb4;
    if (tbase < T1_) {
        float res[12][4];
#pragma unroll
        for (int p = 0; p < 6; p++) {
            float sc0 = d_scale_t[f0 + 2*p],     sh0 = d_shift_t[f0 + 2*p];
            float sc1 = d_scale_t[f0 + 2*p + 1], sh1 = d_shift_t[f0 + 2*p + 1];
#pragma unroll
            for (int t = 0; t < 4; t++) {
                float2 a = unpack2(acc[t][p]);
                res[2*p][t]     = eluf(fmaf(a.x, sc0, sh0));
                res[2*p + 1][t] = eluf(fmaf(a.y, sc1, sh1));
            }
        }
        const bool full = (tbase + 3 < T1_);
#pragma unroll
        for (int fl = 0; fl < 12; fl++) {
            int f = f0 + fl;
            float* row = d_h1 + ((size_t)b * GC_ + (size_t)f * CH_ + ch) * T1P_;
            if (full) {
                *(float4*)&row[tbase] = make_float4(res[fl][0], res[fl][1], res[fl][2], res[fl][3]);
            } else {
#pragma unroll
                for (int t = 0; t < 4; t++)
                    if (tbase + t < T1_) row[tbase + t] = res[fl][t];
            }
        }
    }
}

// ---------------- K2: spatial conv, split-K partials (unchanged from 115us best) ----------------
__global__ void __launch_bounds__(128) k2_spatial(const float* __restrict__ w_s)
{
    __shared__ ull sw[KCHUNK2_][10];       // 9 used + pad
    const int b   = blockIdx.z >> 2;
    const int s   = blockIdx.z & 3;
    const int f0  = blockIdx.y * 18;
    const int t0  = blockIdx.x * 128;
    const int tid = threadIdx.x;
    const int ks0 = s * KCHUNK2_;

    for (int i = tid; i < KCHUNK2_ * 9; i += 128) {
        int k = i / 9, p = i % 9;
        sw[k][p] = pack2(w_s[(size_t)(f0 + 2*p) * GC_ + ks0 + k],
                         w_s[(size_t)(f0 + 2*p + 1) * GC_ + ks0 + k]);
    }
    __syncthreads();

    const int t = t0 + tid;
    const float* hbase = d_h1 + ((size_t)(b * GC_ + ks0)) * T1P_ + t;

    ull acc[9];
#pragma unroll
    for (int p = 0; p < 9; p++) acc[p] = 0ULL;

#pragma unroll 1
    for (int kk = 0; kk < KCHUNK2_; kk += 6) {
        float hv[6];
#pragma unroll
        for (int j = 0; j < 6; j++)
            hv[j] = hbase[(size_t)(kk + j) * T1P_];
#pragma unroll
        for (int j = 0; j < 6; j++) {
            ull hp = pack2(hv[j], hv[j]);
            const ull* wr = &sw[kk + j][0];
            ulonglong2 w01 = *(const ulonglong2*)(wr);
            ulonglong2 w23 = *(const ulonglong2*)(wr + 2);
            ulonglong2 w45 = *(const ulonglong2*)(wr + 4);
            ulonglong2 w67 = *(const ulonglong2*)(wr + 6);
            ull w8 = wr[8];
            fma2(acc[0], hp, w01.x); fma2(acc[1], hp, w01.y);
            fma2(acc[2], hp, w23.x); fma2(acc[3], hp, w23.y);
            fma2(acc[4], hp, w45.x); fma2(acc[5], hp, w45.y);
            fma2(acc[6], hp, w67.x); fma2(acc[7], hp, w67.y);
            fma2(acc[8], hp, w8);
        }
    }

    if (t < T1_) {
        float* pb = d_p2 + ((size_t)s * B_ * F_ + (size_t)b * F_) * T1P_;
#pragma unroll
        for (int p = 0; p < 9; p++) {
            float2 a = unpack2(acc[p]);
            pb[(size_t)(f0 + 2*p) * T1P_ + t]     = a.x;
            pb[(size_t)(f0 + 2*p + 1) * T1P_ + t] = a.y;
        }
    }
}

// ---------------- K2e: reduce partials + BN + ELU + 3-mean -> de-interleaved S_c ----------------
// grid (F, B), block 256.
__global__ void __launch_bounds__(256) k2e_reduce(void)
{
    __shared__ float e[T1P_];
    const int b = blockIdx.y, f = blockIdx.x;
    const int tid = threadIdx.x;
    const size_t row = ((size_t)b * F_ + f) * T1P_;
    const float sc = d_scale_s[f], sh = d_shift_s[f];
    const size_t pstride = (size_t)B_ * F_ * T1P_;

    for (int t = tid; t < T1_; t += 256) {
        float v = d_p2[row + t] + d_p2[pstride + row + t]
                + d_p2[2 * pstride + row + t] + d_p2[3 * pstride + row + t];
        e[t] = eluf(fmaf(v, sc, sh));
    }
    __syncthreads();

    float* Sp = d_Sc + ((size_t)b * F_ + f) * (3 * MS_);
#pragma unroll
    for (int c = 0; c < 3; c++) {
        for (int m = tid; 3 * m + c < SLEN_; m += 256) {
            int t = 3 * m + c;
            Sp[c * MS_ + m] = (e[t] + e[t + 1] + e[t + 2]) * (1.0f / 3.0f);
        }
    }
}

// ---------------- K3: de-interleaved dense conv (len 295, K=15) + BN + ELU -> E_c ----------------
// grid (3 fg, 3 c, B) = 144 blocks, block 128 (1 block/SM, 1 warp/SMSP).
// Thread: 3 consecutive m x 12 f; sliding 3-reg window -> 1 slide-in LDS.64 per (g,j).
__global__ void __launch_bounds__(128) k3_dconv(const float* __restrict__ w_c)
{
    extern __shared__ ull k3s[];
    ull* sS = k3s;                              // [36][MS_] dup (v,v) pairs
    ull (*sw)[6] = (ull(*)[6])(k3s + 36 * MS_); // [36*15][6] f-pairs
    const int f0  = blockIdx.x * 12;
    const int c   = blockIdx.y;
    const int b   = blockIdx.z;
    const int tid = threadIdx.x;

    // load de-interleaved S (dup pairs); zero where 3k+c >= SLEN
    for (int i = tid; i < 36 * MS_; i += 128) {
        int g = i / MS_, k = i % MS_;
        float v = (3 * k + c < SLEN_)
                ? d_Sc[((size_t)b * F_ + g) * (3 * MS_) + c * MS_ + k] : 0.0f;
        sS[i] = pack2(v, v);
    }
    for (int i = tid; i < 36 * KC_ * 6; i += 128) {
        int idx = i / 6, p = i % 6;
        int g = idx / KC_, j = idx % KC_;
        sw[idx][p] = pack2(w_c[((size_t)(f0 + 2*p) * F_ + g) * KC_ + j],
                           w_c[((size_t)(f0 + 2*p + 1) * F_ + g) * KC_ + j]);
    }
    __syncthreads();

    if (tid >= 99) return;                      // 99 threads cover m 0..296 (295 valid)
    const int m0 = 3 * tid;

    ull acc[3][6];
#pragma unroll
    for (int m = 0; m < 3; m++)
#pragma unroll
        for (int p = 0; p < 6; p++) acc[m][p] = 0ULL;

    const ull* Srow = sS;
#pragma unroll 1
    for (int g = 0; g < F_; g++, Srow += MS_) {
        ull s0 = Srow[m0], s1 = Srow[m0 + 1], s2 = Srow[m0 + 2];
        const ull (*wg)[6] = &sw[g * KC_];
#pragma unroll
        for (int j = 0; j < KC_; j++) {
            ulonglong2 w01 = *(const ulonglong2*)&wg[j][0];
            ulonglong2 w23 = *(const ulonglong2*)&wg[j][2];
            ulonglong2 w45 = *(const ulonglong2*)&wg[j][4];
            fma2(acc[0][0], s0, w01.x); fma2(acc[1][0], s1, w01.x); fma2(acc[2][0], s2, w01.x);
            fma2(acc[0][1], s0, w01.y); fma2(acc[1][1], s1, w01.y); fma2(acc[2][1], s2, w01.y);
            fma2(acc[0][2], s0, w23.x); fma2(acc[1][2], s1, w23.x); fma2(acc[2][2], s2, w23.x);
            fma2(acc[0][3], s0, w23.y); fma2(acc[1][3], s1, w23.y); fma2(acc[2][3], s2, w23.y);
            fma2(acc[0][4], s0, w45.x); fma2(acc[1][4], s1, w45.x); fma2(acc[2][4], s2, w45.x);
            fma2(acc[0][5], s0, w45.y); fma2(acc[1][5], s1, w45.y); fma2(acc[2][5], s2, w45.y);
            if (j < KC_ - 1) { s0 = s1; s1 = s2; s2 = Srow[m0 + j + 3]; }
        }
    }

    // BN + ELU epilogue, store E_c
#pragma unroll
    for (int p = 0; p < 6; p++) {
        int fA = f0 + 2*p, fB = fA + 1;
        float scA = d_scale_c[fA], shA = d_shift_c[fA];
        float scB = d_scale_c[fB], shB = d_shift_c[fB];
        float* rA = d_Ec + ((size_t)b * F_ + fA) * (3 * EC_) + c * EC_;
        float* rB = d_Ec + ((size_t)b * F_ + fB) * (3 * EC_) + c * EC_;
#pragma unroll
        for (int mm = 0; mm < 3; mm++) {
            int m = m0 + mm;
            if (m < MC_) {
                float2 a = unpack2(acc[mm][p]);
                rA[m] = eluf(fmaf(a.x, scA, shA));
                rB[m] = eluf(fmaf(a.y, scB, shB));
            }
        }
    }
}

// ---------------- K4: T[m] = sum_c E_c, 296-scan, windowed sums -> G ----------------
// grid (F, B), block 320.
__global__ void __launch_bounds__(320) k4_windows(void)
{
    __shared__ float wsum[10];
    __shared__ float sps[321];
    const int b = blockIdx.y, f = blockIdx.x;
    const int tid = threadIdx.x;
    const int lane = tid & 31, wid = tid >> 5;
    const float* Ep = d_Ec + ((size_t)b * F_ + f) * (3 * EC_);

    float Tv = 0.0f;
    if (tid < MC_)
        Tv = Ep[tid] + Ep[EC_ + tid] + Ep[2 * EC_ + tid];

    // block inclusive scan (10 warps)
    float xv = Tv;
#pragma unroll
    for (int off = 1; off < 32; off <<= 1) {
        float y = __shfl_up_sync(0xffffffffu, xv, off);
        if (lane >= off) xv += y;
    }
    if (lane == 31) wsum[wid] = xv;
    __syncthreads();
    if (wid == 0) {
        float sv = (lane < 10) ? wsum[lane] : 0.0f;
#pragma unroll
        for (int off = 1; off < 16; off <<= 1) {
            float y = __shfl_up_sync(0xffffffffu, sv, off);
            if (lane >= off) sv += y;
        }
        if (lane < 10) wsum[lane] = sv;
    }
    __syncthreads();
    float base = (wid > 0) ? wsum[wid - 1] : 0.0f;
    if (tid < 320 - 1 + 1) sps[tid + 1] = xv + base;   // sps[1..320]
    if (tid == 0) sps[0] = 0.0f;
    __syncthreads();

    if (tid < Q_) {
        int q = tid;
        float s = 0.0f;
#pragma unroll
        for (int r = 0; r < 3; r++)
            s += sps[3 * q + r + 167] - sps[3 * q + r];
        d_G[(size_t)b * FLAT_ + f * Q_ + q] = s * (1.0f / 3.0f);
    }
}

// ---------------- K5: FC reduce ----------------
__global__ void __launch_bounds__(128) k5_fc(
    const float* __restrict__ w_fc, const float* __restrict__ b_fc,
    float* __restrict__ out)
{
    __shared__ float red[OUT_][128];
    const int b = blockIdx.x;
    const int tid = threadIdx.x;

    float p[OUT_];
#pragma unroll
    for (int o = 0; o < OUT_; o++) p[o] = 0.0f;

    for (int i = tid; i < FLAT_; i += 128) {
        float g = d_G[(size_t)b * FLAT_ + i];
#pragma unroll
        for (int o = 0; o < OUT_; o++)
            p[o] = fmaf(g, w_fc[(size_t)o * FLAT_ + i], p[o]);
    }
#pragma unroll
    for (int o = 0; o < OUT_; o++) red[o][tid] = p[o];
    __syncthreads();
    for (int s = 64; s > 0; s >>= 1) {
        if (tid < s) {
#pragma unroll
            for (int o = 0; o < OUT_; o++) red[o][tid] += red[o][tid + s];
        }
        __syncthreads();
    }
    if (tid < OUT_)
        out[b * OUT_ + tid] = red[tid][0] * (1.0f / NCROPS_) + b_fc[tid];
}

// ---------------- launch ----------------
extern "C" void kernel_launch(void* const* d_in, const int* in_sizes, int n_in,
                              void* d_out, int out_size)
{
    const float* x      = (const float*)d_in[0];
    const float* w_t    = (const float*)d_in[1];
    const float* b_t    = (const float*)d_in[2];
    const float* bn_t_g = (const float*)d_in[3];
    const float* bn_t_b = (const float*)d_in[4];
    const float* bn_t_m = (const float*)d_in[5];
    const float* bn_t_v = (const float*)d_in[6];
    const float* w_s    = (const float*)d_in[7];
    const float* b_s    = (const float*)d_in[8];
    const float* bn_s_g = (const float*)d_in[9];
    const float* bn_s_b = (const float*)d_in[10];
    const float* bn_s_m = (const float*)d_in[11];
    const float* bn_s_v = (const float*)d_in[12];
    const float* w_c    = (const float*)d_in[13];
    const float* b_c    = (const float*)d_in[14];
    const float* bn_c_g = (const float*)d_in[15];
    const float* bn_c_b = (const float*)d_in[16];
    const float* bn_c_m = (const float*)d_in[17];
    const float* bn_c_v = (const float*)d_in[18];
    const float* w_fc   = (const float*)d_in[19];
    const float* b_fc   = (const float*)d_in[20];
    float* out = (float*)d_out;

    prep_kernel<<<1, 64>>>(b_t, bn_t_g, bn_t_b, bn_t_m, bn_t_v,
                           b_s, bn_s_g, bn_s_b, bn_s_m, bn_s_v,
                           b_c, bn_c_g, bn_c_b, bn_c_m, bn_c_v);

    dim3 g1(6, CH_, B_);                      // 2112 blocks
    k1_temporal<<<g1, 128>>>(x, w_t);

    dim3 g2(8, 2, B_ * KSPLIT2_);             // 1024 blocks
    k2_spatial<<<g2, 128>>>(w_s);

    dim3 g2e(F_, B_);                         // 576 blocks
    k2e_reduce<<<g2e, 256>>>();

    const int smem3 = (36 * MS_ + 36 * KC_ * 6) * (int)sizeof(ull);  // 115776 B
    cudaFuncSetAttribute(k3_dconv, cudaFuncAttributeMaxDynamicSharedMemorySize, smem3);
    dim3 g3(3, 3, B_);                        // 144 blocks (1/SM)
    k3_dconv<<<g3, 128, smem3>>>(w_c);

    dim3 g4(F_, B_);                          // 576 blocks
    k4_windows<<<g4, 320>>>();

    k5_fc<<<B_, 128>>>(w_fc, b_fc, out);
}

// round 12
// speedup vs baseline: 1.1071x; 1.0553x over previous
#include <cuda_runtime.h>
#include <math.h>

#define B_     16
#define CH_    22
#define T_     1001
#define F_     36
#define KT_    65
#define T1_    937            // T - KT + 1
#define T1P_   944            // padded stride
#define GC_    (F_*CH_)       // 792
#define KC_    15
#define U_     885            // E length
#define SLEN_  935            // S length
#define Q_     43
#define NCROPS_ 501
#define OUT_   4
#define FLAT_  (F_*Q_)        // 1548
#define EPSF   1e-5f

#define KSPLIT2_ 4
#define KCHUNK2_ (GC_/KSPLIT2_)   // 198

// de-interleaved (residue) layout
#define MC_   295             // valid m per residue (all 3 residues have exactly 295)
#define MS_   312             // S_c row stride (floats)
#define EC_   296             // E_c row stride

typedef unsigned long long ull;

// ---------------- scratch (device globals; no allocation) ----------------
__device__ __align__(16) float d_h1[(size_t)B_*GC_*T1P_ + 8192];
__device__ __align__(16) float d_p2[(size_t)KSPLIT2_*B_*F_*T1P_];
__device__ __align__(16) float d_Sc[(size_t)B_*F_*3*MS_];
__device__ __align__(16) float d_Ec[(size_t)B_*F_*3*EC_];

// ---------------- f32x2 helpers ----------------
__device__ __forceinline__ ull pack2(float a, float b) {
    ull r;
    asm("mov.b64 %0, {%1, %2};" : "=l"(r) : "f"(a), "f"(b));
    return r;
}
__device__ __forceinline__ void fma2(ull& d, ull a, ull b) {
    asm("fma.rn.f32x2 %0, %1, %2, %0;" : "+l"(d) : "l"(a), "l"(b));
}
__device__ __forceinline__ float2 unpack2(ull v) {
    float2 r;
    asm("mov.b64 {%0, %1}, %2;" : "=f"(r.x), "=f"(r.y) : "l"(v));
    return r;
}
__device__ __forceinline__ float eluf(float x) {
    return x > 0.0f ? x : (__expf(x) - 1.0f);
}

// ---------------- K1: temporal conv + BN + ELU (BN folded per block) ----------------
// grid (2*3, CH, B), block 128. Thread: 4 consecutive t x 12 f (6 f32x2 pairs).
__global__ void __launch_bounds__(128) k1_temporal(
    const float* __restrict__ x, const float* __restrict__ w_t,
    const float* __restrict__ b_t, const float* __restrict__ g_t,
    const float* __restrict__ bb_t, const float* __restrict__ m_t,
    const float* __restrict__ v_t)
{
    __shared__ float sx[512 + 64];         // 576
    __shared__ ull   sw[KT_][6];           // f32x2 weight pairs
    __shared__ float ssc[12], ssh[12];
    const int b   = blockIdx.z;
    const int ch  = blockIdx.y;
    const int tb  = blockIdx.x / 3;
    const int fg  = blockIdx.x % 3;
    const int f0  = fg * 12;
    const int t0  = tb * 512;
    const int tid = threadIdx.x;

    for (int i = tid; i < KT_ * 6; i += 128) {
        int k = i / 6, p = i % 6;
        sw[k][p] = pack2(w_t[(f0 + 2*p) * KT_ + k],
                         w_t[(f0 + 2*p + 1) * KT_ + k]);
    }
    const float* xp = x + ((size_t)b * CH_ + ch) * T_;
    for (int i = tid; i < 576; i += 128) {
        int tg = t0 + i;
        sx[i] = (tg < T_) ? xp[tg] : 0.0f;
    }
    if (tid < 12) {
        int f = f0 + tid;
        float inv = g_t[f] / sqrtf(v_t[f] + EPSF);
        ssc[tid] = inv;
        ssh[tid] = (b_t[f] - m_t[f]) * inv + bb_t[f];
    }
    __syncthreads();

    ull acc[4][6];
#pragma unroll
    for (int m = 0; m < 4; m++)
#pragma unroll
        for (int p = 0; p < 6; p++) acc[m][p] = 0ULL;

    const int tb4 = tid * 4;
#pragma unroll 5
    for (int k = 0; k < KT_; k++) {
        float x0 = sx[tb4 + k];
        float x1 = sx[tb4 + k + 1];
        float x2 = sx[tb4 + k + 2];
        float x3 = sx[tb4 + k + 3];
        ull xp0 = pack2(x0, x0), xp1 = pack2(x1, x1);
        ull xp2 = pack2(x2, x2), xp3 = pack2(x3, x3);
        ulonglong2 w01 = *(const ulonglong2*)&sw[k][0];
        ulonglong2 w23 = *(const ulonglong2*)&sw[k][2];
        ulonglong2 w45 = *(const ulonglong2*)&sw[k][4];
        ull wv[6] = {w01.x, w01.y, w23.x, w23.y, w45.x, w45.y};
#pragma unroll
        for (int p = 0; p < 6; p++) {
            fma2(acc[0][p], xp0, wv[p]);
            fma2(acc[1][p], xp1, wv[p]);
            fma2(acc[2][p], xp2, wv[p]);
            fma2(acc[3][p], xp3, wv[p]);
        }
    }

    const int tbase = t0 + tb4;
    if (tbase < T1_) {
        float res[12][4];
#pragma unroll
        for (int p = 0; p < 6; p++) {
            float sc0 = ssc[2*p],     sh0 = ssh[2*p];
            float sc1 = ssc[2*p + 1], sh1 = ssh[2*p + 1];
#pragma unroll
            for (int t = 0; t < 4; t++) {
                float2 a = unpack2(acc[t][p]);
                res[2*p][t]     = eluf(fmaf(a.x, sc0, sh0));
                res[2*p + 1][t] = eluf(fmaf(a.y, sc1, sh1));
            }
        }
        const bool full = (tbase + 3 < T1_);
#pragma unroll
        for (int fl = 0; fl < 12; fl++) {
            int f = f0 + fl;
            float* row = d_h1 + ((size_t)b * GC_ + (size_t)f * CH_ + ch) * T1P_;
            if (full) {
                *(float4*)&row[tbase] = make_float4(res[fl][0], res[fl][1], res[fl][2], res[fl][3]);
            } else {
#pragma unroll
                for (int t = 0; t < 4; t++)
                    if (tbase + t < T1_) row[tbase + t] = res[fl][t];
            }
        }
    }
}

// ---------------- K2: spatial conv, split-K partials (unchanged, proven) ----------------
__global__ void __launch_bounds__(128) k2_spatial(const float* __restrict__ w_s)
{
    __shared__ ull sw[KCHUNK2_][10];       // 9 used + pad
    const int b   = blockIdx.z >> 2;
    const int s   = blockIdx.z & 3;
    const int f0  = blockIdx.y * 18;
    const int t0  = blockIdx.x * 128;
    const int tid = threadIdx.x;
    const int ks0 = s * KCHUNK2_;

    for (int i = tid; i < KCHUNK2_ * 9; i += 128) {
        int k = i / 9, p = i % 9;
        sw[k][p] = pack2(w_s[(size_t)(f0 + 2*p) * GC_ + ks0 + k],
                         w_s[(size_t)(f0 + 2*p + 1) * GC_ + ks0 + k]);
    }
    __syncthreads();

    const int t = t0 + tid;
    const float* hbase = d_h1 + ((size_t)(b * GC_ + ks0)) * T1P_ + t;

    ull acc[9];
#pragma unroll
    for (int p = 0; p < 9; p++) acc[p] = 0ULL;

#pragma unroll 1
    for (int kk = 0; kk < KCHUNK2_; kk += 6) {
        float hv[6];
#pragma unroll
        for (int j = 0; j < 6; j++)
            hv[j] = hbase[(size_t)(kk + j) * T1P_];
#pragma unroll
        for (int j = 0; j < 6; j++) {
            ull hp = pack2(hv[j], hv[j]);
            const ull* wr = &sw[kk + j][0];
            ulonglong2 w01 = *(const ulonglong2*)(wr);
            ulonglong2 w23 = *(const ulonglong2*)(wr + 2);
            ulonglong2 w45 = *(const ulonglong2*)(wr + 4);
            ulonglong2 w67 = *(const ulonglong2*)(wr + 6);
            ull w8 = wr[8];
            fma2(acc[0], hp, w01.x); fma2(acc[1], hp, w01.y);
            fma2(acc[2], hp, w23.x); fma2(acc[3], hp, w23.y);
            fma2(acc[4], hp, w45.x); fma2(acc[5], hp, w45.y);
            fma2(acc[6], hp, w67.x); fma2(acc[7], hp, w67.y);
            fma2(acc[8], hp, w8);
        }
    }

    if (t < T1_) {
        float* pb = d_p2 + ((size_t)s * B_ * F_ + (size_t)b * F_) * T1P_;
#pragma unroll
        for (int p = 0; p < 9; p++) {
            float2 a = unpack2(acc[p]);
            pb[(size_t)(f0 + 2*p) * T1P_ + t]     = a.x;
            pb[(size_t)(f0 + 2*p + 1) * T1P_ + t] = a.y;
        }
    }
}

// ---------------- K2e: reduce partials (float4) + BN + ELU + 3-mean -> S_c ----------------
// grid (F, B), block 256.
__global__ void __launch_bounds__(256) k2e_reduce(
    const float* __restrict__ b_s, const float* __restrict__ g_s,
    const float* __restrict__ bb_s, const float* __restrict__ m_s,
    const float* __restrict__ v_s)
{
    __shared__ float e[T1P_];
    const int b = blockIdx.y, f = blockIdx.x;
    const int tid = threadIdx.x;
    const size_t row = ((size_t)b * F_ + f) * T1P_;
    const size_t pstride = (size_t)B_ * F_ * T1P_;

    float inv = g_s[f] / sqrtf(v_s[f] + EPSF);
    const float sc = inv;
    const float sh = (b_s[f] - m_s[f]) * inv + bb_s[f];

    if (tid < T1P_ / 4) {
        float4 v0 = *(const float4*)&d_p2[row + 4 * tid];
        float4 v1 = *(const float4*)&d_p2[pstride + row + 4 * tid];
        float4 v2 = *(const float4*)&d_p2[2 * pstride + row + 4 * tid];
        float4 v3 = *(const float4*)&d_p2[3 * pstride + row + 4 * tid];
        float4 r;
        r.x = eluf(fmaf(v0.x + v1.x + v2.x + v3.x, sc, sh));
        r.y = eluf(fmaf(v0.y + v1.y + v2.y + v3.y, sc, sh));
        r.z = eluf(fmaf(v0.z + v1.z + v2.z + v3.z, sc, sh));
        r.w = eluf(fmaf(v0.w + v1.w + v2.w + v3.w, sc, sh));
        *(float4*)&e[4 * tid] = r;
    }
    __syncthreads();

    float* Sp = d_Sc + ((size_t)b * F_ + f) * (3 * MS_);
#pragma unroll
    for (int c = 0; c < 3; c++) {
        for (int m = tid; 3 * m + c < SLEN_; m += 256) {
            int t = 3 * m + c;
            Sp[c * MS_ + m] = (e[t] + e[t + 1] + e[t + 2]) * (1.0f / 3.0f);
        }
    }
}

// ---------------- K3: de-interleaved dense conv (len 295, K=15) + BN + ELU -> E_c ----------------
// grid (3 fg, 3 c, B) = 144 blocks, block 128. BN folded per block.
__global__ void __launch_bounds__(128) k3_dconv(
    const float* __restrict__ w_c,
    const float* __restrict__ b_c, const float* __restrict__ g_c,
    const float* __restrict__ bb_c, const float* __restrict__ m_c,
    const float* __restrict__ v_c)
{
    extern __shared__ ull k3s[];
    ull* sS = k3s;                              // [36][MS_] dup (v,v) pairs
    ull (*sw)[6] = (ull(*)[6])(k3s + 36 * MS_); // [36*15][6] f-pairs
    __shared__ float ssc[12], ssh[12];
    const int f0  = blockIdx.x * 12;
    const int c   = blockIdx.y;
    const int b   = blockIdx.z;
    const int tid = threadIdx.x;

    for (int i = tid; i < 36 * MS_; i += 128) {
        int g = i / MS_, k = i % MS_;
        float v = (3 * k + c < SLEN_)
                ? d_Sc[((size_t)b * F_ + g) * (3 * MS_) + c * MS_ + k] : 0.0f;
        sS[i] = pack2(v, v);
    }
    for (int i = tid; i < 36 * KC_ * 6; i += 128) {
        int idx = i / 6, p = i % 6;
        int g = idx / KC_, j = idx % KC_;
        sw[idx][p] = pack2(w_c[((size_t)(f0 + 2*p) * F_ + g) * KC_ + j],
                           w_c[((size_t)(f0 + 2*p + 1) * F_ + g) * KC_ + j]);
    }
    if (tid < 12) {
        int f = f0 + tid;
        float inv = g_c[f] / sqrtf(v_c[f] + EPSF);
        ssc[tid] = inv;
        ssh[tid] = (b_c[f] - m_c[f]) * inv + bb_c[f];
    }
    __syncthreads();

    if (tid >= 99) return;                      // 99 threads cover m 0..296 (295 valid)
    const int m0 = 3 * tid;

    ull acc[3][6];
#pragma unroll
    for (int m = 0; m < 3; m++)
#pragma unroll
        for (int p = 0; p < 6; p++) acc[m][p] = 0ULL;

    const ull* Srow = sS;
#pragma unroll 1
    for (int g = 0; g < F_; g++, Srow += MS_) {
        ull s0 = Srow[m0], s1 = Srow[m0 + 1], s2 = Srow[m0 + 2];
        const ull (*wg)[6] = &sw[g * KC_];
#pragma unroll
        for (int j = 0; j < KC_; j++) {
            ulonglong2 w01 = *(const ulonglong2*)&wg[j][0];
            ulonglong2 w23 = *(const ulonglong2*)&wg[j][2];
            ulonglong2 w45 = *(const ulonglong2*)&wg[j][4];
            fma2(acc[0][0], s0, w01.x); fma2(acc[1][0], s1, w01.x); fma2(acc[2][0], s2, w01.x);
            fma2(acc[0][1], s0, w01.y); fma2(acc[1][1], s1, w01.y); fma2(acc[2][1], s2, w01.y);
            fma2(acc[0][2], s0, w23.x); fma2(acc[1][2], s1, w23.x); fma2(acc[2][2], s2, w23.x);
            fma2(acc[0][3], s0, w23.y); fma2(acc[1][3], s1, w23.y); fma2(acc[2][3], s2, w23.y);
            fma2(acc[0][4], s0, w45.x); fma2(acc[1][4], s1, w45.x); fma2(acc[2][4], s2, w45.x);
            fma2(acc[0][5], s0, w45.y); fma2(acc[1][5], s1, w45.y); fma2(acc[2][5], s2, w45.y);
            if (j < KC_ - 1) { s0 = s1; s1 = s2; s2 = Srow[m0 + j + 3]; }
        }
    }

#pragma unroll
    for (int p = 0; p < 6; p++) {
        int fA = f0 + 2*p, fB = fA + 1;
        float scA = ssc[2*p],     shA = ssh[2*p];
        float scB = ssc[2*p + 1], shB = ssh[2*p + 1];
        float* rA = d_Ec + ((size_t)b * F_ + fA) * (3 * EC_) + c * EC_;
        float* rB = d_Ec + ((size_t)b * F_ + fB) * (3 * EC_) + c * EC_;
#pragma unroll
        for (int mm = 0; mm < 3; mm++) {
            int m = m0 + mm;
            if (m < MC_) {
                float2 a = unpack2(acc[mm][p]);
                rA[m] = eluf(fmaf(a.x, scA, shA));
                rB[m] = eluf(fmaf(a.y, scB, shB));
            }
        }
    }
}

// ---------------- K45: per-b scans + windowed sums + FC, fused ----------------
// grid (B), block 1024. Warp w handles rows f = w, w+32.
__global__ void __launch_bounds__(1024) k45_fc(
    const float* __restrict__ w_fc, const float* __restrict__ b_fc,
    float* __restrict__ out)
{
    __shared__ float sps[F_][304];    // [f][m+1]; sps[f][0]=0; indices 0..295 used
    __shared__ float red[32][OUT_];
    const int b = blockIdx.x;
    const int tid = threadIdx.x;
    const int lane = tid & 31, wid = tid >> 5;

    for (int f = wid; f < F_; f += 32) {
        const float* Ep = d_Ec + ((size_t)b * F_ + f) * (3 * EC_);
        // segmented scan: lane owns m in [lane*10, lane*10+10)
        float loc[10];
        const int m0 = lane * 10;
        float lsum = 0.0f;
#pragma unroll
        for (int k = 0; k < 10; k++) {
            int m = m0 + k;
            loc[k] = (m < MC_) ? (Ep[m] + Ep[EC_ + m] + Ep[2 * EC_ + m]) : 0.0f;
            lsum += loc[k];
        }
        float ex = lsum;
#pragma unroll
        for (int off = 1; off < 32; off <<= 1) {
            float y = __shfl_up_sync(0xffffffffu, ex, off);
            if (lane >= off) ex += y;
        }
        ex -= lsum;                    // exclusive prefix of lane sums
        float run = ex;
#pragma unroll
        for (int k = 0; k < 10; k++) {
            run += loc[k];
            int m = m0 + k;
            if (m < MC_) sps[f][m + 1] = run;
        }
        if (lane == 0) sps[f][0] = 0.0f;
    }
    __syncthreads();

    float p[OUT_] = {0.0f, 0.0f, 0.0f, 0.0f};
    for (int i = tid; i < FLAT_; i += 1024) {
        int f = i / Q_, q = i % Q_;
        float gsum = 0.0f;
#pragma unroll
        for (int r = 0; r < 3; r++)
            gsum += sps[f][3 * q + r + 167] - sps[f][3 * q + r];
        gsum *= (1.0f / 3.0f);
#pragma unroll
        for (int o = 0; o < OUT_; o++)
            p[o] = fmaf(gsum, w_fc[(size_t)o * FLAT_ + i], p[o]);
    }

#pragma unroll
    for (int o = 0; o < OUT_; o++) {
        float v = p[o];
#pragma unroll
        for (int off = 16; off > 0; off >>= 1)
            v += __shfl_down_sync(0xffffffffu, v, off);
        if (lane == 0) red[wid][o] = v;
    }
    __syncthreads();
    if (wid == 0) {
#pragma unroll
        for (int o = 0; o < OUT_; o++) {
            float v = red[lane][o];
#pragma unroll
            for (int off = 16; off > 0; off >>= 1)
                v += __shfl_down_sync(0xffffffffu, v, off);
            if (lane == 0)
                out[b * OUT_ + o] = v * (1.0f / NCROPS_) + b_fc[o];
        }
    }
}

// ---------------- launch ----------------
extern "C" void kernel_launch(void* const* d_in, const int* in_sizes, int n_in,
                              void* d_out, int out_size)
{
    const float* x      = (const float*)d_in[0];
    const float* w_t    = (const float*)d_in[1];
    const float* b_t    = (const float*)d_in[2];
    const float* bn_t_g = (const float*)d_in[3];
    const float* bn_t_b = (const float*)d_in[4];
    const float* bn_t_m = (const float*)d_in[5];
    const float* bn_t_v = (const float*)d_in[6];
    const float* w_s    = (const float*)d_in[7];
    const float* b_s    = (const float*)d_in[8];
    const float* bn_s_g = (const float*)d_in[9];
    const float* bn_s_b = (const float*)d_in[10];
    const float* bn_s_m = (const float*)d_in[11];
    const float* bn_s_v = (const float*)d_in[12];
    const float* w_c    = (const float*)d_in[13];
    const float* b_c    = (const float*)d_in[14];
    const float* bn_c_g = (const float*)d_in[15];
    const float* bn_c_b = (const float*)d_in[16];
    const float* bn_c_m = (const float*)d_in[17];
    const float* bn_c_v = (const float*)d_in[18];
    const float* w_fc   = (const float*)d_in[19];
    const float* b_fc   = (const float*)d_in[20];
    float* out = (float*)d_out;

    dim3 g1(6, CH_, B_);                      // 2112 blocks
    k1_temporal<<<g1, 128>>>(x, w_t, b_t, bn_t_g, bn_t_b, bn_t_m, bn_t_v);

    dim3 g2(8, 2, B_ * KSPLIT2_);             // 1024 blocks
    k2_spatial<<<g2, 128>>>(w_s);

    dim3 g2e(F_, B_);                         // 576 blocks
    k2e_reduce<<<g2e, 256>>>(b_s, bn_s_g, bn_s_b, bn_s_m, bn_s_v);

    const int smem3 = (36 * MS_ + 36 * KC_ * 6) * (int)sizeof(ull);  // 115776 B
    cudaFuncSetAttribute(k3_dconv, cudaFuncAttributeMaxDynamicSharedMemorySize, smem3);
    dim3 g3(3, 3, B_);                        // 144 blocks
    k3_dconv<<<g3, 128, smem3>>>(w_c, b_c, bn_c_g, bn_c_b, bn_c_m, bn_c_v);

    k45_fc<<<B_, 1024>>>(w_fc, b_fc, out);
}